// round 2
// baseline (speedup 1.0000x reference)
#include <cuda_runtime.h>
#include <cuda_bf16.h>

#define N_NODES 4096
#define NS 128
#define NV 16
#define H 8
#define D 16
#define COMB 144
#define HD 128   // H*D

typedef unsigned long long u64;

// ---- packed f32x2 helpers (sm_100+ PTX; ptxas never emits these from C++) ----
__device__ __forceinline__ u64 pack2(float lo, float hi) {
    u64 d; asm("mov.b64 %0, {%1, %2};" : "=l"(d) : "f"(lo), "f"(hi)); return d;
}
__device__ __forceinline__ void unpack2(u64 x, float& lo, float& hi) {
    asm("mov.b64 {%0, %1}, %2;" : "=f"(lo), "=f"(hi) : "l"(x));
}
__device__ __forceinline__ u64 fma2(u64 a, u64 b, u64 c) {
    u64 d; asm("fma.rn.f32x2 %0, %1, %2, %3;" : "=l"(d) : "l"(a), "l"(b), "l"(c)); return d;
}
__device__ __forceinline__ u64 mul2(u64 a, u64 b) {
    u64 d; asm("mul.rn.f32x2 %0, %1, %2;" : "=l"(d) : "l"(a), "l"(b)); return d;
}
__device__ __forceinline__ u64 add2(u64 a, u64 b) {
    u64 d; asm("add.rn.f32x2 %0, %1, %2;" : "=l"(d) : "l"(a), "l"(b)); return d;
}
__device__ __forceinline__ float ex2f(float x) {
    float y; asm("ex2.approx.f32 %0, %1;" : "=f"(y) : "f"(x)); return y;
}

// Scratch (static device globals — no allocation allowed)
__device__ float g_q[N_NODES * HD];
__device__ float g_k[N_NODES * HD];
__device__ float g_v[N_NODES * HD];
__device__ float g_attn[N_NODES * HD];

// ---------------------------------------------------------------------------
// Kernel 1: projections, 8 nodes per block. comb stored transposed [i][node]
// so node-pairs are packed f32x2 operands; each weight is loaded once per
// 8 nodes instead of once per node.
// ---------------------------------------------------------------------------
#define PNODES 8
__global__ void proj_kernel(const float* __restrict__ s, const float* __restrict__ v,
                            const float* __restrict__ Wq, const float* __restrict__ bq,
                            const float* __restrict__ Wk, const float* __restrict__ bk,
                            const float* __restrict__ Wv, const float* __restrict__ bv) {
    const int nb = blockIdx.x * PNODES;
    const int t = threadIdx.x;
    __shared__ __align__(16) float comb_t[COMB][PNODES];

    for (int idx = t; idx < COMB * PNODES; idx += 128) {
        const int j = idx & 7;
        const int i = idx >> 3;
        float val;
        if (i < NS) {
            val = s[(nb + j) * NS + i];
        } else {
            const int vi = i - NS;
            const float* vp = &v[(nb + j) * NV * 3 + vi * 3];
            float x = vp[0], y = vp[1], z = vp[2];
            val = sqrtf(fmaxf(x * x + y * y + z * z, 1e-8f));
        }
        comb_t[i][j] = val;
    }
    __syncthreads();

    const float bqv = bq[t], bkv = bk[t], bvv = bv[t];
    u64 aq[4], ak[4], av[4];
#pragma unroll
    for (int jj = 0; jj < 4; jj++) {
        aq[jj] = pack2(bqv, bqv);
        ak[jj] = pack2(bkv, bkv);
        av[jj] = pack2(bvv, bvv);
    }

#pragma unroll 4
    for (int i = 0; i < COMB; i++) {
        const float wq = Wq[i * HD + t];
        const float wk = Wk[i * HD + t];
        const u64 wq2 = pack2(wq, wq);
        const u64 wk2 = pack2(wk, wk);
        const ulonglong2* cr = (const ulonglong2*)comb_t[i];
        const ulonglong2 ca = cr[0], cb = cr[1];
        aq[0] = fma2(wq2, ca.x, aq[0]); aq[1] = fma2(wq2, ca.y, aq[1]);
        aq[2] = fma2(wq2, cb.x, aq[2]); aq[3] = fma2(wq2, cb.y, aq[3]);
        ak[0] = fma2(wk2, ca.x, ak[0]); ak[1] = fma2(wk2, ca.y, ak[1]);
        ak[2] = fma2(wk2, cb.x, ak[2]); ak[3] = fma2(wk2, cb.y, ak[3]);
    }
#pragma unroll 4
    for (int i = 0; i < NS; i++) {
        const float wv = Wv[i * HD + t];
        const u64 wv2 = pack2(wv, wv);
        const ulonglong2* cr = (const ulonglong2*)comb_t[i];
        const ulonglong2 ca = cr[0], cb = cr[1];
        av[0] = fma2(wv2, ca.x, av[0]); av[1] = fma2(wv2, ca.y, av[1]);
        av[2] = fma2(wv2, cb.x, av[2]); av[3] = fma2(wv2, cb.y, av[3]);
    }

#pragma unroll
    for (int jj = 0; jj < 4; jj++) {
        float lo, hi;
        unpack2(aq[jj], lo, hi);
        g_q[(nb + 2 * jj) * HD + t] = lo; g_q[(nb + 2 * jj + 1) * HD + t] = hi;
        unpack2(ak[jj], lo, hi);
        g_k[(nb + 2 * jj) * HD + t] = lo; g_k[(nb + 2 * jj + 1) * HD + t] = hi;
        unpack2(av[jj], lo, hi);
        g_v[(nb + 2 * jj) * HD + t] = lo; g_v[(nb + 2 * jj + 1) * HD + t] = hi;
    }
}

// ---------------------------------------------------------------------------
// Kernel 2: flash-style dense attention (no-max softmax, validated safe).
// One thread = one query; K/V streamed through smem in 128-key tiles.
// All dot/PV math in packed f32x2 (2 FLOPs/issue). scale*log2e folded into q
// so the softmax exp is a bare ex2.approx.
// ---------------------------------------------------------------------------
__global__ void attn_kernel() {
    const int h = blockIdx.y;
    const int t = threadIdx.x;
    const int n = blockIdx.x * 128 + t;

    __shared__ __align__(16) u64 sk[128 * 8];
    __shared__ __align__(16) u64 sv[128 * 8];

    // q pre-scaled by D^-0.5 * log2(e)
    const float c = 0.25f * 1.4426950408889634f;
    u64 q2[8];
    {
        const float4* qp = (const float4*)&g_q[n * HD + h * D];
#pragma unroll
        for (int j = 0; j < 4; j++) {
            float4 f = qp[j];
            q2[2 * j]     = pack2(f.x * c, f.y * c);
            q2[2 * j + 1] = pack2(f.z * c, f.w * c);
        }
    }

    u64 acc[8];
#pragma unroll
    for (int j = 0; j < 8; j++) acc[j] = 0ULL;
    float l = 0.f;

    for (int kt = 0; kt < N_NODES; kt += 128) {
        __syncthreads();
        {
            const ulonglong2* kp = (const ulonglong2*)&g_k[(kt + t) * HD + h * D];
            const ulonglong2* vp = (const ulonglong2*)&g_v[(kt + t) * HD + h * D];
            ulonglong2* skd = (ulonglong2*)&sk[t * 8];
            ulonglong2* svd = (ulonglong2*)&sv[t * 8];
#pragma unroll
            for (int j = 0; j < 4; j++) { skd[j] = kp[j]; svd[j] = vp[j]; }
        }
        __syncthreads();

#pragma unroll 4
        for (int m = 0; m < 128; m++) {
            const ulonglong2* kr = (const ulonglong2*)&sk[m * 8];
            const ulonglong2 k01 = kr[0], k23 = kr[1], k45 = kr[2], k67 = kr[3];
            u64 d0 = mul2(q2[0], k01.x);
            u64 d1 = mul2(q2[1], k01.y);
            u64 d2 = mul2(q2[2], k23.x);
            u64 d3 = mul2(q2[3], k23.y);
            d0 = fma2(q2[4], k45.x, d0);
            d1 = fma2(q2[5], k45.y, d1);
            d2 = fma2(q2[6], k67.x, d2);
            d3 = fma2(q2[7], k67.y, d3);
            d0 = add2(d0, d1);
            d2 = add2(d2, d3);
            d0 = add2(d0, d2);
            float lo, hi;
            unpack2(d0, lo, hi);
            const float p = ex2f(lo + hi);   // exp(dot * scale)
            l += p;
            const u64 pp = pack2(p, p);
            const ulonglong2* vr = (const ulonglong2*)&sv[m * 8];
            const ulonglong2 v01 = vr[0], v23 = vr[1], v45 = vr[2], v67 = vr[3];
            acc[0] = fma2(pp, v01.x, acc[0]);
            acc[1] = fma2(pp, v01.y, acc[1]);
            acc[2] = fma2(pp, v23.x, acc[2]);
            acc[3] = fma2(pp, v23.y, acc[3]);
            acc[4] = fma2(pp, v45.x, acc[4]);
            acc[5] = fma2(pp, v45.y, acc[5]);
            acc[6] = fma2(pp, v67.x, acc[6]);
            acc[7] = fma2(pp, v67.y, acc[7]);
        }
    }

    const float inv = 1.f / l;
    float2* op = (float2*)&g_attn[n * HD + h * D];
#pragma unroll
    for (int j = 0; j < 8; j++) {
        float lo, hi;
        unpack2(acc[j], lo, hi);
        op[j] = make_float2(lo * inv, hi * inv);
    }
}

// ---------------------------------------------------------------------------
// Kernel 3: out proj + residual + LayerNorm. 4 nodes per block; Wo loaded
// once per 4 nodes; LN reductions done 4-wide via float4 trees.
// ---------------------------------------------------------------------------
#define ONODES 4
__global__ void out_kernel(const float* __restrict__ s,
                           const float* __restrict__ Wo, const float* __restrict__ bo,
                           const float* __restrict__ gamma, const float* __restrict__ beta,
                           float* __restrict__ out) {
    const int nb = blockIdx.x * ONODES;
    const int t = threadIdx.x;
    __shared__ __align__(16) float a_t[HD][ONODES];
    __shared__ float4 red[128];

    for (int idx = t; idx < HD * ONODES; idx += 128) {
        const int j = idx & 3;
        const int i = idx >> 2;
        a_t[i][j] = g_attn[(nb + j) * HD + i];
    }
    __syncthreads();

    const float bov = bo[t];
    u64 acc2[2];
    acc2[0] = pack2(bov, bov);
    acc2[1] = pack2(bov, bov);

#pragma unroll 8
    for (int i = 0; i < HD; i++) {
        const float w = Wo[i * NS + t];
        const u64 w2 = pack2(w, w);
        const ulonglong2 cv = *(const ulonglong2*)a_t[i];
        acc2[0] = fma2(w2, cv.x, acc2[0]);
        acc2[1] = fma2(w2, cv.y, acc2[1]);
    }

    float val[4];
    unpack2(acc2[0], val[0], val[1]);
    unpack2(acc2[1], val[2], val[3]);
#pragma unroll
    for (int j = 0; j < 4; j++) val[j] += s[(nb + j) * NS + t];

    // mean (4 nodes at once)
    red[t] = make_float4(val[0], val[1], val[2], val[3]);
    __syncthreads();
#pragma unroll
    for (int off = 64; off > 0; off >>= 1) {
        if (t < off) {
            float4 a = red[t], b = red[t + off];
            red[t] = make_float4(a.x + b.x, a.y + b.y, a.z + b.z, a.w + b.w);
        }
        __syncthreads();
    }
    const float4 mu4 = red[0];
    const float mu[4] = { mu4.x * (1.f / 128.f), mu4.y * (1.f / 128.f),
                          mu4.z * (1.f / 128.f), mu4.w * (1.f / 128.f) };
    __syncthreads();

    // variance
    float dv[4];
#pragma unroll
    for (int j = 0; j < 4; j++) dv[j] = val[j] - mu[j];
    red[t] = make_float4(dv[0] * dv[0], dv[1] * dv[1], dv[2] * dv[2], dv[3] * dv[3]);
    __syncthreads();
#pragma unroll
    for (int off = 64; off > 0; off >>= 1) {
        if (t < off) {
            float4 a = red[t], b = red[t + off];
            red[t] = make_float4(a.x + b.x, a.y + b.y, a.z + b.z, a.w + b.w);
        }
        __syncthreads();
    }
    const float4 var4 = red[0];
    const float var[4] = { var4.x * (1.f / 128.f), var4.y * (1.f / 128.f),
                           var4.z * (1.f / 128.f), var4.w * (1.f / 128.f) };

    const float g = gamma[t], b = beta[t];
#pragma unroll
    for (int j = 0; j < 4; j++) {
        out[(nb + j) * NS + t] = dv[j] * rsqrtf(var[j] + 1e-5f) * g + b;
    }
}

// ---------------------------------------------------------------------------
extern "C" void kernel_launch(void* const* d_in, const int* in_sizes, int n_in,
                              void* d_out, int out_size) {
    const float* s     = (const float*)d_in[0];
    const float* v     = (const float*)d_in[1];
    const float* Wq    = (const float*)d_in[2];
    const float* bq    = (const float*)d_in[3];
    const float* Wk    = (const float*)d_in[4];
    const float* bk    = (const float*)d_in[5];
    const float* Wv    = (const float*)d_in[6];
    const float* bv    = (const float*)d_in[7];
    const float* Wo    = (const float*)d_in[8];
    const float* bo    = (const float*)d_in[9];
    const float* gamma = (const float*)d_in[10];
    const float* beta  = (const float*)d_in[11];
    float* out = (float*)d_out;

    proj_kernel<<<N_NODES / PNODES, 128>>>(s, v, Wq, bq, Wk, bk, Wv, bv);
    attn_kernel<<<dim3(N_NODES / 128, H), 128>>>();
    out_kernel<<<N_NODES / ONODES, 128>>>(s, Wo, bo, gamma, beta, out);

    // v passes through unchanged: second element of the output tuple
    cudaMemcpyAsync(out + N_NODES * NS, v, N_NODES * NV * 3 * sizeof(float),
                    cudaMemcpyDeviceToDevice, 0);
}

// round 3
// speedup vs baseline: 1.9584x; 1.9584x over previous
#include <cuda_runtime.h>
#include <cuda_bf16.h>
#include <cstdint>

#define N_NODES 4096
#define NS 128
#define NV 16
#define H 8
#define D 16
#define COMB 144
#define HD 128   // H*D

typedef unsigned long long u64;

// ---- packed f32x2 helpers (kept for proj, where they measured a win) ----
__device__ __forceinline__ u64 pack2(float lo, float hi) {
    u64 d; asm("mov.b64 %0, {%1, %2};" : "=l"(d) : "f"(lo), "f"(hi)); return d;
}
__device__ __forceinline__ void unpack2(u64 x, float& lo, float& hi) {
    asm("mov.b64 {%0, %1}, %2;" : "=f"(lo), "=f"(hi) : "l"(x));
}
__device__ __forceinline__ u64 fma2(u64 a, u64 b, u64 c) {
    u64 d; asm("fma.rn.f32x2 %0, %1, %2, %3;" : "=l"(d) : "l"(a), "l"(b), "l"(c)); return d;
}
__device__ __forceinline__ float ex2f(float x) {
    float y; asm("ex2.approx.f32 %0, %1;" : "=f"(y) : "f"(x)); return y;
}
// ---- tf32 mma helpers ----
__device__ __forceinline__ uint32_t f2tf32(float x) {
    uint32_t r; asm("cvt.rna.tf32.f32 %0, %1;" : "=r"(r) : "f"(x)); return r;
}
__device__ __forceinline__ void mma_tf32(float* d, const uint32_t* a, uint32_t b0, uint32_t b1) {
    asm("mma.sync.aligned.m16n8k8.row.col.f32.tf32.tf32.f32 "
        "{%0,%1,%2,%3},{%4,%5,%6,%7},{%8,%9},{%0,%1,%2,%3};"
        : "+f"(d[0]), "+f"(d[1]), "+f"(d[2]), "+f"(d[3])
        : "r"(a[0]), "r"(a[1]), "r"(a[2]), "r"(a[3]), "r"(b0), "r"(b1));
}

// Scratch (static device globals — no allocation allowed)
__device__ float g_q[N_NODES * HD];
__device__ float g_k[N_NODES * HD];
__device__ float g_v[N_NODES * HD];
__device__ float g_attn[N_NODES * HD];

// ---------------------------------------------------------------------------
// Kernel 1: projections, 4 nodes per block (1024 blocks for occupancy).
// comb stored transposed [i][node]; node-pairs as packed f32x2 operands.
// ---------------------------------------------------------------------------
#define PNODES 4
__global__ void proj_kernel(const float* __restrict__ s, const float* __restrict__ v,
                            const float* __restrict__ Wq, const float* __restrict__ bq,
                            const float* __restrict__ Wk, const float* __restrict__ bk,
                            const float* __restrict__ Wv, const float* __restrict__ bv) {
    const int nb = blockIdx.x * PNODES;
    const int t = threadIdx.x;
    __shared__ __align__(16) float comb_t[COMB][PNODES];

    for (int idx = t; idx < COMB * PNODES; idx += 128) {
        const int j = idx & 3;
        const int i = idx >> 2;
        float val;
        if (i < NS) {
            val = s[(nb + j) * NS + i];
        } else {
            const int vi = i - NS;
            const float* vp = &v[(nb + j) * NV * 3 + vi * 3];
            float x = vp[0], y = vp[1], z = vp[2];
            val = sqrtf(fmaxf(x * x + y * y + z * z, 1e-8f));
        }
        comb_t[i][j] = val;
    }
    __syncthreads();

    const float bqv = bq[t], bkv = bk[t], bvv = bv[t];
    u64 aq[2], ak[2], av[2];
    aq[0] = pack2(bqv, bqv); aq[1] = aq[0];
    ak[0] = pack2(bkv, bkv); ak[1] = ak[0];
    av[0] = pack2(bvv, bvv); av[1] = av[0];

#pragma unroll 4
    for (int i = 0; i < COMB; i++) {
        const float wq = Wq[i * HD + t];
        const float wk = Wk[i * HD + t];
        const u64 wq2 = pack2(wq, wq);
        const u64 wk2 = pack2(wk, wk);
        const ulonglong2 cv = *(const ulonglong2*)comb_t[i];
        aq[0] = fma2(wq2, cv.x, aq[0]); aq[1] = fma2(wq2, cv.y, aq[1]);
        ak[0] = fma2(wk2, cv.x, ak[0]); ak[1] = fma2(wk2, cv.y, ak[1]);
    }
#pragma unroll 4
    for (int i = 0; i < NS; i++) {
        const float wv = Wv[i * HD + t];
        const u64 wv2 = pack2(wv, wv);
        const ulonglong2 cv = *(const ulonglong2*)comb_t[i];
        av[0] = fma2(wv2, cv.x, av[0]); av[1] = fma2(wv2, cv.y, av[1]);
    }

#pragma unroll
    for (int jj = 0; jj < 2; jj++) {
        float lo, hi;
        unpack2(aq[jj], lo, hi);
        g_q[(nb + 2 * jj) * HD + t] = lo; g_q[(nb + 2 * jj + 1) * HD + t] = hi;
        unpack2(ak[jj], lo, hi);
        g_k[(nb + 2 * jj) * HD + t] = lo; g_k[(nb + 2 * jj + 1) * HD + t] = hi;
        unpack2(av[jj], lo, hi);
        g_v[(nb + 2 * jj) * HD + t] = lo; g_v[(nb + 2 * jj + 1) * HD + t] = hi;
    }
}

// ---------------------------------------------------------------------------
// Kernel 2: tensor-core flash attention (tf32 m16n8k8, fp32 accumulate).
// Block = 64 queries x 1 head, 4 warps; warp owns 16 query rows.
// K/V streamed through smem in 128-key tiles, pre-converted to tf32.
// No-max softmax (validated rel_err 8.7e-8 in fp32): p = ex2(S'), S' has
// D^-0.5 * log2(e) folded into Q.
// Smem pads: K rows 20 words (g*20+tid hits 32 distinct banks),
//            V rows 24 words (tid*24+g hits 32 distinct banks).
// ---------------------------------------------------------------------------
#define KPAD 20
#define VPAD 24
__global__ void attn_kernel() {
    const int h = blockIdx.y;
    const int qbase = blockIdx.x * 64;
    const int t = threadIdx.x;          // 0..127
    const int w = t >> 5;
    const int lane = t & 31;
    const int g = lane >> 2;            // 0..7
    const int tid = lane & 3;           // 0..3

    __shared__ uint32_t Ks[128 * KPAD];
    __shared__ uint32_t Vs[128 * VPAD];

    // Q fragments (2 k-chunks of d), pre-scaled by D^-0.5 * log2(e)
    const float cs = 0.25f * 1.4426950408889634f;
    uint32_t qa[2][4];
    {
        const float* Q = &g_q[(qbase + w * 16) * HD + h * D];
#pragma unroll
        for (int c = 0; c < 2; c++) {
            qa[c][0] = f2tf32(Q[g * HD       + c * 8 + tid]     * cs);
            qa[c][1] = f2tf32(Q[(g + 8) * HD + c * 8 + tid]     * cs);
            qa[c][2] = f2tf32(Q[g * HD       + c * 8 + tid + 4] * cs);
            qa[c][3] = f2tf32(Q[(g + 8) * HD + c * 8 + tid + 4] * cs);
        }
    }

    float o0[4] = {0.f, 0.f, 0.f, 0.f};   // O cols [0..7]  for rows g, g+8
    float o1[4] = {0.f, 0.f, 0.f, 0.f};   // O cols [8..15]
    float l0 = 0.f, l1 = 0.f;             // row sums (rows g, g+8), quad-partial
    const int s0 = (lane & ~3) | (tid >> 1);
    const int s1 = s0 + 2;
    const bool odd = (tid & 1);

    for (int kt = 0; kt < N_NODES; kt += 128) {
        __syncthreads();
        {
            const float4* kp = (const float4*)&g_k[(kt + t) * HD + h * D];
            const float4* vp = (const float4*)&g_v[(kt + t) * HD + h * D];
#pragma unroll
            for (int i = 0; i < 4; i++) {
                float4 kk = kp[i], vv = vp[i];
                uint4 ku = make_uint4(f2tf32(kk.x), f2tf32(kk.y), f2tf32(kk.z), f2tf32(kk.w));
                uint4 vu = make_uint4(f2tf32(vv.x), f2tf32(vv.y), f2tf32(vv.z), f2tf32(vv.w));
                *(uint4*)&Ks[t * KPAD + 4 * i] = ku;
                *(uint4*)&Vs[t * VPAD + 4 * i] = vu;
            }
        }
        __syncthreads();

#pragma unroll
        for (int j = 0; j < 16; j++) {        // 8-key ntile
            // S = Q K^T (scaled, log2 domain)
            float sc[4] = {0.f, 0.f, 0.f, 0.f};
#pragma unroll
            for (int c = 0; c < 2; c++) {
                const uint32_t b0 = Ks[(8 * j + g) * KPAD + 8 * c + tid];
                const uint32_t b1 = Ks[(8 * j + g) * KPAD + 8 * c + tid + 4];
                mma_tf32(sc, qa[c], b0, b1);
            }
            // softmax numerator
            const float p0 = ex2f(sc[0]), p1 = ex2f(sc[1]);
            const float p2 = ex2f(sc[2]), p3 = ex2f(sc[3]);
            l0 += p0 + p1;
            l1 += p2 + p3;
            // permute C-layout (cols 2tid,2tid+1) -> A-layout (cols tid,tid+4)
            const float u00 = __shfl_sync(0xffffffffu, p0, s0);
            const float u01 = __shfl_sync(0xffffffffu, p1, s0);
            const float u10 = __shfl_sync(0xffffffffu, p0, s1);
            const float u11 = __shfl_sync(0xffffffffu, p1, s1);
            const float u20 = __shfl_sync(0xffffffffu, p2, s0);
            const float u21 = __shfl_sync(0xffffffffu, p3, s0);
            const float u30 = __shfl_sync(0xffffffffu, p2, s1);
            const float u31 = __shfl_sync(0xffffffffu, p3, s1);
            uint32_t af[4];
            af[0] = f2tf32(odd ? u01 : u00);   // row g,   col tid
            af[1] = f2tf32(odd ? u21 : u20);   // row g+8, col tid
            af[2] = f2tf32(odd ? u11 : u10);   // row g,   col tid+4
            af[3] = f2tf32(odd ? u31 : u30);   // row g+8, col tid+4
            // O += P V
            const uint32_t vb0 = Vs[(8 * j + tid) * VPAD + g];
            const uint32_t vb1 = Vs[(8 * j + tid + 4) * VPAD + g];
            mma_tf32(o0, af, vb0, vb1);
            const uint32_t vb2 = Vs[(8 * j + tid) * VPAD + g + 8];
            const uint32_t vb3 = Vs[(8 * j + tid + 4) * VPAD + g + 8];
            mma_tf32(o1, af, vb2, vb3);
        }
    }

    // reduce row sums across the quad
    l0 += __shfl_xor_sync(0xffffffffu, l0, 1);
    l0 += __shfl_xor_sync(0xffffffffu, l0, 2);
    l1 += __shfl_xor_sync(0xffffffffu, l1, 1);
    l1 += __shfl_xor_sync(0xffffffffu, l1, 2);
    const float i0 = 1.f / l0;
    const float i1 = 1.f / l1;

    float* O0 = &g_attn[(qbase + w * 16 + g) * HD + h * D];
    float* O1 = &g_attn[(qbase + w * 16 + g + 8) * HD + h * D];
    *(float2*)&O0[2 * tid]     = make_float2(o0[0] * i0, o0[1] * i0);
    *(float2*)&O1[2 * tid]     = make_float2(o0[2] * i1, o0[3] * i1);
    *(float2*)&O0[2 * tid + 8] = make_float2(o1[0] * i0, o1[1] * i0);
    *(float2*)&O1[2 * tid + 8] = make_float2(o1[2] * i1, o1[3] * i1);
}

// ---------------------------------------------------------------------------
// Kernel 3: out proj + residual + LayerNorm. 4 nodes per block.
// ---------------------------------------------------------------------------
#define ONODES 4
__global__ void out_kernel(const float* __restrict__ s,
                           const float* __restrict__ Wo, const float* __restrict__ bo,
                           const float* __restrict__ gamma, const float* __restrict__ beta,
                           float* __restrict__ out) {
    const int nb = blockIdx.x * ONODES;
    const int t = threadIdx.x;
    __shared__ __align__(16) float a_t[HD][ONODES];
    __shared__ float4 red[128];

    for (int idx = t; idx < HD * ONODES; idx += 128) {
        const int j = idx & 3;
        const int i = idx >> 2;
        a_t[i][j] = g_attn[(nb + j) * HD + i];
    }
    __syncthreads();

    const float bov = bo[t];
    u64 acc2[2];
    acc2[0] = pack2(bov, bov);
    acc2[1] = acc2[0];

#pragma unroll 8
    for (int i = 0; i < HD; i++) {
        const float w = Wo[i * NS + t];
        const u64 w2 = pack2(w, w);
        const ulonglong2 cv = *(const ulonglong2*)a_t[i];
        acc2[0] = fma2(w2, cv.x, acc2[0]);
        acc2[1] = fma2(w2, cv.y, acc2[1]);
    }

    float val[4];
    unpack2(acc2[0], val[0], val[1]);
    unpack2(acc2[1], val[2], val[3]);
#pragma unroll
    for (int j = 0; j < 4; j++) val[j] += s[(nb + j) * NS + t];

    red[t] = make_float4(val[0], val[1], val[2], val[3]);
    __syncthreads();
#pragma unroll
    for (int off = 64; off > 0; off >>= 1) {
        if (t < off) {
            float4 a = red[t], b = red[t + off];
            red[t] = make_float4(a.x + b.x, a.y + b.y, a.z + b.z, a.w + b.w);
        }
        __syncthreads();
    }
    const float4 mu4 = red[0];
    const float mu[4] = { mu4.x * (1.f / 128.f), mu4.y * (1.f / 128.f),
                          mu4.z * (1.f / 128.f), mu4.w * (1.f / 128.f) };
    __syncthreads();

    float dv[4];
#pragma unroll
    for (int j = 0; j < 4; j++) dv[j] = val[j] - mu[j];
    red[t] = make_float4(dv[0] * dv[0], dv[1] * dv[1], dv[2] * dv[2], dv[3] * dv[3]);
    __syncthreads();
#pragma unroll
    for (int off = 64; off > 0; off >>= 1) {
        if (t < off) {
            float4 a = red[t], b = red[t + off];
            red[t] = make_float4(a.x + b.x, a.y + b.y, a.z + b.z, a.w + b.w);
        }
        __syncthreads();
    }
    const float4 var4 = red[0];
    const float var[4] = { var4.x * (1.f / 128.f), var4.y * (1.f / 128.f),
                           var4.z * (1.f / 128.f), var4.w * (1.f / 128.f) };

    const float gm = gamma[t], bt = beta[t];
#pragma unroll
    for (int j = 0; j < 4; j++) {
        out[(nb + j) * NS + t] = dv[j] * rsqrtf(var[j] + 1e-5f) * gm + bt;
    }
}

// ---------------------------------------------------------------------------
extern "C" void kernel_launch(void* const* d_in, const int* in_sizes, int n_in,
                              void* d_out, int out_size) {
    const float* s     = (const float*)d_in[0];
    const float* v     = (const float*)d_in[1];
    const float* Wq    = (const float*)d_in[2];
    const float* bq    = (const float*)d_in[3];
    const float* Wk    = (const float*)d_in[4];
    const float* bk    = (const float*)d_in[5];
    const float* Wv    = (const float*)d_in[6];
    const float* bv    = (const float*)d_in[7];
    const float* Wo    = (const float*)d_in[8];
    const float* bo    = (const float*)d_in[9];
    const float* gamma = (const float*)d_in[10];
    const float* beta  = (const float*)d_in[11];
    float* out = (float*)d_out;

    proj_kernel<<<N_NODES / PNODES, 128>>>(s, v, Wq, bq, Wk, bk, Wv, bv);
    attn_kernel<<<dim3(N_NODES / 64, H), 128>>>();
    out_kernel<<<N_NODES / ONODES, 128>>>(s, Wo, bo, gamma, beta, out);

    // v passes through unchanged: second element of the output tuple
    cudaMemcpyAsync(out + N_NODES * NS, v, N_NODES * NV * 3 * sizeof(float),
                    cudaMemcpyDeviceToDevice, 0);
}

// round 4
// speedup vs baseline: 2.6550x; 1.3557x over previous
#include <cuda_runtime.h>
#include <cuda_bf16.h>
#include <cstdint>

#define N_NODES 4096
#define NS 128
#define NV 16
#define H 8
#define D 16
#define COMB 144
#define HD 128   // H*D

typedef unsigned long long u64;

// ---- packed f32x2 helpers (proj/out only, where they measured a win) ----
__device__ __forceinline__ u64 pack2(float lo, float hi) {
    u64 d; asm("mov.b64 %0, {%1, %2};" : "=l"(d) : "f"(lo), "f"(hi)); return d;
}
__device__ __forceinline__ void unpack2(u64 x, float& lo, float& hi) {
    asm("mov.b64 {%0, %1}, %2;" : "=f"(lo), "=f"(hi) : "l"(x));
}
__device__ __forceinline__ u64 fma2(u64 a, u64 b, u64 c) {
    u64 d; asm("fma.rn.f32x2 %0, %1, %2, %3;" : "=l"(d) : "l"(a), "l"(b), "l"(c)); return d;
}
__device__ __forceinline__ float ex2f(float x) {
    float y; asm("ex2.approx.f32 %0, %1;" : "=f"(y) : "f"(x)); return y;
}
// ---- tf32 mma helpers ----
__device__ __forceinline__ uint32_t f2tf32(float x) {
    uint32_t r; asm("cvt.rna.tf32.f32 %0, %1;" : "=r"(r) : "f"(x)); return r;
}
__device__ __forceinline__ void mma_tf32(float* d, const uint32_t* a, uint32_t b0, uint32_t b1) {
    asm("mma.sync.aligned.m16n8k8.row.col.f32.tf32.tf32.f32 "
        "{%0,%1,%2,%3},{%4,%5,%6,%7},{%8,%9},{%0,%1,%2,%3};"
        : "+f"(d[0]), "+f"(d[1]), "+f"(d[2]), "+f"(d[3])
        : "r"(a[0]), "r"(a[1]), "r"(a[2]), "r"(a[3]), "r"(b0), "r"(b1));
}

// Scratch (static device globals — no allocation allowed)
__device__ float g_q[N_NODES * HD];
__device__ float g_k[N_NODES * HD];
__device__ float g_v[N_NODES * HD];
__device__ float g_attn[N_NODES * HD];

// ---------------------------------------------------------------------------
// Kernel 1: projections, 8 nodes per block (measured-best config, 39.6us).
// comb stored transposed [i][node]; node-pairs as packed f32x2 operands.
// ---------------------------------------------------------------------------
#define PNODES 8
__global__ void proj_kernel(const float* __restrict__ s, const float* __restrict__ v,
                            const float* __restrict__ Wq, const float* __restrict__ bq,
                            const float* __restrict__ Wk, const float* __restrict__ bk,
                            const float* __restrict__ Wv, const float* __restrict__ bv) {
    const int nb = blockIdx.x * PNODES;
    const int t = threadIdx.x;
    __shared__ __align__(16) float comb_t[COMB][PNODES];

    for (int idx = t; idx < COMB * PNODES; idx += 128) {
        const int j = idx & 7;
        const int i = idx >> 3;
        float val;
        if (i < NS) {
            val = s[(nb + j) * NS + i];
        } else {
            const int vi = i - NS;
            const float* vp = &v[(nb + j) * NV * 3 + vi * 3];
            float x = vp[0], y = vp[1], z = vp[2];
            val = sqrtf(fmaxf(x * x + y * y + z * z, 1e-8f));
        }
        comb_t[i][j] = val;
    }
    __syncthreads();

    const float bqv = bq[t], bkv = bk[t], bvv = bv[t];
    u64 aq[4], ak[4], av[4];
#pragma unroll
    for (int jj = 0; jj < 4; jj++) {
        aq[jj] = pack2(bqv, bqv);
        ak[jj] = pack2(bkv, bkv);
        av[jj] = pack2(bvv, bvv);
    }

#pragma unroll 4
    for (int i = 0; i < COMB; i++) {
        const float wq = Wq[i * HD + t];
        const float wk = Wk[i * HD + t];
        const u64 wq2 = pack2(wq, wq);
        const u64 wk2 = pack2(wk, wk);
        const ulonglong2* cr = (const ulonglong2*)comb_t[i];
        const ulonglong2 ca = cr[0], cb = cr[1];
        aq[0] = fma2(wq2, ca.x, aq[0]); aq[1] = fma2(wq2, ca.y, aq[1]);
        aq[2] = fma2(wq2, cb.x, aq[2]); aq[3] = fma2(wq2, cb.y, aq[3]);
        ak[0] = fma2(wk2, ca.x, ak[0]); ak[1] = fma2(wk2, ca.y, ak[1]);
        ak[2] = fma2(wk2, cb.x, ak[2]); ak[3] = fma2(wk2, cb.y, ak[3]);
    }
#pragma unroll 4
    for (int i = 0; i < NS; i++) {
        const float wv = Wv[i * HD + t];
        const u64 wv2 = pack2(wv, wv);
        const ulonglong2* cr = (const ulonglong2*)comb_t[i];
        const ulonglong2 ca = cr[0], cb = cr[1];
        av[0] = fma2(wv2, ca.x, av[0]); av[1] = fma2(wv2, ca.y, av[1]);
        av[2] = fma2(wv2, cb.x, av[2]); av[3] = fma2(wv2, cb.y, av[3]);
    }

#pragma unroll
    for (int jj = 0; jj < 4; jj++) {
        float lo, hi;
        unpack2(aq[jj], lo, hi);
        g_q[(nb + 2 * jj) * HD + t] = lo; g_q[(nb + 2 * jj + 1) * HD + t] = hi;
        unpack2(ak[jj], lo, hi);
        g_k[(nb + 2 * jj) * HD + t] = lo; g_k[(nb + 2 * jj + 1) * HD + t] = hi;
        unpack2(av[jj], lo, hi);
        g_v[(nb + 2 * jj) * HD + t] = lo; g_v[(nb + 2 * jj + 1) * HD + t] = hi;
    }
}

// ---------------------------------------------------------------------------
// Kernel 2: tensor-core flash attention (tf32 m16n8k8, fp32 accumulate).
// Block = 64 queries x 1 head, 4 warps; warp owns 16 query rows.
// SHUFFLE-FREE softmax->PV handoff: the S-mma C-layout (cols 2tid, 2tid+1)
// is reused directly as the PV-mma A-layout under the column permutation
// pi(j) = 2j (j<4), 2(j-4)+1 (j>=4); V's B-fragment rows are fetched
// permuted (rows 8j+2tid, 8j+2tid+1) to match. Valid because
// sum_j P[r][pi(j)] V[pi(j)][n] = (PV)[r][n] for any permutation.
// PAD=20 words/row: K-frag (g*20+tid), V-frag (40tid+g / 40tid+20+g) and
// uint4 stores (stride 20) all hit 32 distinct banks.
// ---------------------------------------------------------------------------
#define PAD 20
__global__ void attn_kernel() {
    const int h = blockIdx.y;
    const int qbase = blockIdx.x * 64;
    const int t = threadIdx.x;          // 0..127
    const int w = t >> 5;
    const int lane = t & 31;
    const int g = lane >> 2;            // 0..7
    const int tid = lane & 3;           // 0..3

    __shared__ uint32_t Ks[128 * PAD];
    __shared__ uint32_t Vs[128 * PAD];

    // Q fragments (2 k-chunks of d), pre-scaled by D^-0.5 * log2(e)
    const float cs = 0.25f * 1.4426950408889634f;
    uint32_t qa[2][4];
    {
        const float* Q = &g_q[(qbase + w * 16) * HD + h * D];
#pragma unroll
        for (int c = 0; c < 2; c++) {
            qa[c][0] = f2tf32(Q[g * HD       + c * 8 + tid]     * cs);
            qa[c][1] = f2tf32(Q[(g + 8) * HD + c * 8 + tid]     * cs);
            qa[c][2] = f2tf32(Q[g * HD       + c * 8 + tid + 4] * cs);
            qa[c][3] = f2tf32(Q[(g + 8) * HD + c * 8 + tid + 4] * cs);
        }
    }

    float o0[4] = {0.f, 0.f, 0.f, 0.f};   // O cols [0..7]  for rows g, g+8
    float o1[4] = {0.f, 0.f, 0.f, 0.f};   // O cols [8..15]
    float l0 = 0.f, l1 = 0.f;             // row sums (rows g, g+8), quad-partial

    for (int kt = 0; kt < N_NODES; kt += 128) {
        __syncthreads();
        {
            const float4* kp = (const float4*)&g_k[(kt + t) * HD + h * D];
            const float4* vp = (const float4*)&g_v[(kt + t) * HD + h * D];
#pragma unroll
            for (int i = 0; i < 4; i++) {
                float4 kk = kp[i], vv = vp[i];
                uint4 ku = make_uint4(f2tf32(kk.x), f2tf32(kk.y), f2tf32(kk.z), f2tf32(kk.w));
                uint4 vu = make_uint4(f2tf32(vv.x), f2tf32(vv.y), f2tf32(vv.z), f2tf32(vv.w));
                *(uint4*)&Ks[t * PAD + 4 * i] = ku;
                *(uint4*)&Vs[t * PAD + 4 * i] = vu;
            }
        }
        __syncthreads();

#pragma unroll
        for (int j = 0; j < 16; j++) {        // 8-key ntile
            // S = Q K^T (scaled, log2 domain)
            float sc[4] = {0.f, 0.f, 0.f, 0.f};
#pragma unroll
            for (int c = 0; c < 2; c++) {
                const uint32_t b0 = Ks[(8 * j + g) * PAD + 8 * c + tid];
                const uint32_t b1 = Ks[(8 * j + g) * PAD + 8 * c + tid + 4];
                mma_tf32(sc, qa[c], b0, b1);
            }
            // softmax numerator: p_i = ex2(S'), C-layout cols 2tid, 2tid+1
            const float p0 = ex2f(sc[0]), p1 = ex2f(sc[1]);
            const float p2 = ex2f(sc[2]), p3 = ex2f(sc[3]);
            l0 += p0 + p1;
            l1 += p2 + p3;
            // direct C->A reuse under permutation pi (no shuffles):
            // a0=(row g, "col" tid)=P[g][2tid]=p0, a1=P[g+8][2tid]=p2,
            // a2=(row g, "col" tid+4)=P[g][2tid+1]=p1, a3=P[g+8][2tid+1]=p3
            uint32_t af[4];
            af[0] = f2tf32(p0);
            af[1] = f2tf32(p2);
            af[2] = f2tf32(p1);
            af[3] = f2tf32(p3);
            // O += P V, with V rows permuted to match: row j' -> key pi(j')
            const uint32_t vb0 = Vs[(8 * j + 2 * tid)     * PAD + g];
            const uint32_t vb1 = Vs[(8 * j + 2 * tid + 1) * PAD + g];
            mma_tf32(o0, af, vb0, vb1);
            const uint32_t vb2 = Vs[(8 * j + 2 * tid)     * PAD + g + 8];
            const uint32_t vb3 = Vs[(8 * j + 2 * tid + 1) * PAD + g + 8];
            mma_tf32(o1, af, vb2, vb3);
        }
    }

    // reduce row sums across the quad
    l0 += __shfl_xor_sync(0xffffffffu, l0, 1);
    l0 += __shfl_xor_sync(0xffffffffu, l0, 2);
    l1 += __shfl_xor_sync(0xffffffffu, l1, 1);
    l1 += __shfl_xor_sync(0xffffffffu, l1, 2);
    const float i0 = 1.f / l0;
    const float i1 = 1.f / l1;

    float* O0 = &g_attn[(qbase + w * 16 + g) * HD + h * D];
    float* O1 = &g_attn[(qbase + w * 16 + g + 8) * HD + h * D];
    *(float2*)&O0[2 * tid]     = make_float2(o0[0] * i0, o0[1] * i0);
    *(float2*)&O1[2 * tid]     = make_float2(o0[2] * i1, o0[3] * i1);
    *(float2*)&O0[2 * tid + 8] = make_float2(o1[0] * i0, o1[1] * i0);
    *(float2*)&O1[2 * tid + 8] = make_float2(o1[2] * i1, o1[3] * i1);
}

// ---------------------------------------------------------------------------
// Kernel 3: out proj + residual + LayerNorm. 4 nodes per block.
// ---------------------------------------------------------------------------
#define ONODES 4
__global__ void out_kernel(const float* __restrict__ s,
                           const float* __restrict__ Wo, const float* __restrict__ bo,
                           const float* __restrict__ gamma, const float* __restrict__ beta,
                           float* __restrict__ out) {
    const int nb = blockIdx.x * ONODES;
    const int t = threadIdx.x;
    __shared__ __align__(16) float a_t[HD][ONODES];
    __shared__ float4 red[128];

    for (int idx = t; idx < HD * ONODES; idx += 128) {
        const int j = idx & 3;
        const int i = idx >> 2;
        a_t[i][j] = g_attn[(nb + j) * HD + i];
    }
    __syncthreads();

    const float bov = bo[t];
    u64 acc2[2];
    acc2[0] = pack2(bov, bov);
    acc2[1] = acc2[0];

#pragma unroll 8
    for (int i = 0; i < HD; i++) {
        const float w = Wo[i * NS + t];
        const u64 w2 = pack2(w, w);
        const ulonglong2 cv = *(const ulonglong2*)a_t[i];
        acc2[0] = fma2(w2, cv.x, acc2[0]);
        acc2[1] = fma2(w2, cv.y, acc2[1]);
    }

    float val[4];
    unpack2(acc2[0], val[0], val[1]);
    unpack2(acc2[1], val[2], val[3]);
#pragma unroll
    for (int j = 0; j < 4; j++) val[j] += s[(nb + j) * NS + t];

    red[t] = make_float4(val[0], val[1], val[2], val[3]);
    __syncthreads();
#pragma unroll
    for (int off = 64; off > 0; off >>= 1) {
        if (t < off) {
            float4 a = red[t], b = red[t + off];
            red[t] = make_float4(a.x + b.x, a.y + b.y, a.z + b.z, a.w + b.w);
        }
        __syncthreads();
    }
    const float4 mu4 = red[0];
    const float mu[4] = { mu4.x * (1.f / 128.f), mu4.y * (1.f / 128.f),
                          mu4.z * (1.f / 128.f), mu4.w * (1.f / 128.f) };
    __syncthreads();

    float dv[4];
#pragma unroll
    for (int j = 0; j < 4; j++) dv[j] = val[j] - mu[j];
    red[t] = make_float4(dv[0] * dv[0], dv[1] * dv[1], dv[2] * dv[2], dv[3] * dv[3]);
    __syncthreads();
#pragma unroll
    for (int off = 64; off > 0; off >>= 1) {
        if (t < off) {
            float4 a = red[t], b = red[t + off];
            red[t] = make_float4(a.x + b.x, a.y + b.y, a.z + b.z, a.w + b.w);
        }
        __syncthreads();
    }
    const float4 var4 = red[0];
    const float var[4] = { var4.x * (1.f / 128.f), var4.y * (1.f / 128.f),
                           var4.z * (1.f / 128.f), var4.w * (1.f / 128.f) };

    const float gm = gamma[t], bt = beta[t];
#pragma unroll
    for (int j = 0; j < 4; j++) {
        out[(nb + j) * NS + t] = dv[j] * rsqrtf(var[j] + 1e-5f) * gm + bt;
    }
}

// ---------------------------------------------------------------------------
extern "C" void kernel_launch(void* const* d_in, const int* in_sizes, int n_in,
                              void* d_out, int out_size) {
    const float* s     = (const float*)d_in[0];
    const float* v     = (const float*)d_in[1];
    const float* Wq    = (const float*)d_in[2];
    const float* bq    = (const float*)d_in[3];
    const float* Wk    = (const float*)d_in[4];
    const float* bk    = (const float*)d_in[5];
    const float* Wv    = (const float*)d_in[6];
    const float* bv    = (const float*)d_in[7];
    const float* Wo    = (const float*)d_in[8];
    const float* bo    = (const float*)d_in[9];
    const float* gamma = (const float*)d_in[10];
    const float* beta  = (const float*)d_in[11];
    float* out = (float*)d_out;

    proj_kernel<<<N_NODES / PNODES, 128>>>(s, v, Wq, bq, Wk, bk, Wv, bv);
    attn_kernel<<<dim3(N_NODES / 64, H), 128>>>();
    out_kernel<<<N_NODES / ONODES, 128>>>(s, Wo, bo, gamma, beta, out);

    // v passes through unchanged: second element of the output tuple
    cudaMemcpyAsync(out + N_NODES * NS, v, N_NODES * NV * 3 * sizeof(float),
                    cudaMemcpyDeviceToDevice, 0);
}

// round 5
// speedup vs baseline: 3.6884x; 1.3892x over previous
#include <cuda_runtime.h>
#include <cuda_fp16.h>
#include <cstdint>

#define N_NODES 4096
#define NS 128
#define NV 16
#define H 8
#define D 16
#define COMB 144
#define HD 128   // H*D

typedef unsigned long long u64;

// ---- packed f32x2 helpers (proj/out GEMVs) ----
__device__ __forceinline__ u64 pack2(float lo, float hi) {
    u64 d; asm("mov.b64 %0, {%1, %2};" : "=l"(d) : "f"(lo), "f"(hi)); return d;
}
__device__ __forceinline__ void unpack2(u64 x, float& lo, float& hi) {
    asm("mov.b64 {%0, %1}, %2;" : "=f"(lo), "=f"(hi) : "l"(x));
}
__device__ __forceinline__ u64 fma2(u64 a, u64 b, u64 c) {
    u64 d; asm("fma.rn.f32x2 %0, %1, %2, %3;" : "=l"(d) : "l"(a), "l"(b), "l"(c)); return d;
}
// ---- f16 mma (m16n8k16, fp32 accumulate) ----
__device__ __forceinline__ void mma_f16(float* d, const uint32_t* a, uint32_t b0, uint32_t b1) {
    asm("mma.sync.aligned.m16n8k16.row.col.f32.f16.f16.f32 "
        "{%0,%1,%2,%3},{%4,%5,%6,%7},{%8,%9},{%0,%1,%2,%3};"
        : "+f"(d[0]), "+f"(d[1]), "+f"(d[2]), "+f"(d[3])
        : "r"(a[0]), "r"(a[1]), "r"(a[2]), "r"(a[3]), "r"(b0), "r"(b1));
}
__device__ __forceinline__ uint32_t h2bits(__half2 h) {
    return *reinterpret_cast<uint32_t*>(&h);
}

// Scratch (static device globals — no allocation allowed)
__device__ __half g_qh[N_NODES * HD];   // q * (D^-0.5 * log2e), f16, [node][ch]
__device__ __half g_kh[N_NODES * HD];   // k, f16, [node][ch]
__device__ __half g_vth[HD * N_NODES];  // v, f16, TRANSPOSED [ch][node]
__device__ float  g_attn[N_NODES * HD];

// ---------------------------------------------------------------------------
// Kernel 1: projections, 8 nodes/block, weights staged through smem in
// 16-row tiles (kills the 416 latency-exposed LDGs/thread of the old version).
// Emits q (pre-scaled f16), k (f16), v (f16 transposed [ch][node]).
// ---------------------------------------------------------------------------
#define PNODES 8
__global__ void proj_kernel(const float* __restrict__ s, const float* __restrict__ v,
                            const float* __restrict__ Wq, const float* __restrict__ bq,
                            const float* __restrict__ Wk, const float* __restrict__ bk,
                            const float* __restrict__ Wv, const float* __restrict__ bv) {
    const int nb = blockIdx.x * PNODES;
    const int t = threadIdx.x;
    __shared__ __align__(16) float comb_t[COMB][PNODES];
    __shared__ __align__(16) float wsm[2][16 * 128];

    for (int idx = t; idx < COMB * PNODES; idx += 128) {
        const int j = idx & 7;
        const int i = idx >> 3;
        float val;
        if (i < NS) {
            val = s[(nb + j) * NS + i];
        } else {
            const int vi = i - NS;
            const float* vp = &v[(nb + j) * NV * 3 + vi * 3];
            float x = vp[0], y = vp[1], z = vp[2];
            val = sqrtf(fmaxf(x * x + y * y + z * z, 1e-8f));
        }
        comb_t[i][j] = val;
    }

    const float bqv = bq[t], bkv = bk[t], bvv = bv[t];
    u64 aq[4], ak[4], av[4];
#pragma unroll
    for (int jj = 0; jj < 4; jj++) {
        aq[jj] = pack2(bqv, bqv);
        ak[jj] = pack2(bkv, bkv);
        av[jj] = pack2(bvv, bvv);
    }

    // Phase A: Wq + Wk over COMB=144 (9 tiles of 16 rows)
    for (int kt = 0; kt < 9; kt++) {
        __syncthreads();
        {
            const float4* sq4 = (const float4*)(Wq + kt * 16 * 128);
            const float4* sk4 = (const float4*)(Wk + kt * 16 * 128);
            float4* dq = (float4*)wsm[0];
            float4* dk = (float4*)wsm[1];
#pragma unroll
            for (int p = 0; p < 4; p++) {
                dq[t + p * 128] = sq4[t + p * 128];
                dk[t + p * 128] = sk4[t + p * 128];
            }
        }
        __syncthreads();
#pragma unroll
        for (int ii = 0; ii < 16; ii++) {
            const int i = kt * 16 + ii;
            const float wq = wsm[0][ii * 128 + t];
            const float wk = wsm[1][ii * 128 + t];
            const u64 wq2 = pack2(wq, wq);
            const u64 wk2 = pack2(wk, wk);
            const ulonglong2* cr = (const ulonglong2*)comb_t[i];
            const ulonglong2 ca = cr[0], cb = cr[1];
            aq[0] = fma2(wq2, ca.x, aq[0]); aq[1] = fma2(wq2, ca.y, aq[1]);
            aq[2] = fma2(wq2, cb.x, aq[2]); aq[3] = fma2(wq2, cb.y, aq[3]);
            ak[0] = fma2(wk2, ca.x, ak[0]); ak[1] = fma2(wk2, ca.y, ak[1]);
            ak[2] = fma2(wk2, cb.x, ak[2]); ak[3] = fma2(wk2, cb.y, ak[3]);
        }
    }
    // Phase B: Wv over NS=128 (8 tiles of 16 rows)
    for (int kt = 0; kt < 8; kt++) {
        __syncthreads();
        {
            const float4* sv4 = (const float4*)(Wv + kt * 16 * 128);
            float4* dv = (float4*)wsm[0];
#pragma unroll
            for (int p = 0; p < 4; p++) dv[t + p * 128] = sv4[t + p * 128];
        }
        __syncthreads();
#pragma unroll
        for (int ii = 0; ii < 16; ii++) {
            const int i = kt * 16 + ii;
            const float wv = wsm[0][ii * 128 + t];
            const u64 wv2 = pack2(wv, wv);
            const ulonglong2* cr = (const ulonglong2*)comb_t[i];
            const ulonglong2 ca = cr[0], cb = cr[1];
            av[0] = fma2(wv2, ca.x, av[0]); av[1] = fma2(wv2, ca.y, av[1]);
            av[2] = fma2(wv2, cb.x, av[2]); av[3] = fma2(wv2, cb.y, av[3]);
        }
    }

    const float CS = 0.25f * 1.4426950408889634f;  // D^-0.5 * log2(e), folded into q
#pragma unroll
    for (int jj = 0; jj < 4; jj++) {
        float lo, hi;
        unpack2(aq[jj], lo, hi);
        g_qh[(nb + 2 * jj) * HD + t]     = __float2half(lo * CS);
        g_qh[(nb + 2 * jj + 1) * HD + t] = __float2half(hi * CS);
        unpack2(ak[jj], lo, hi);
        g_kh[(nb + 2 * jj) * HD + t]     = __float2half(lo);
        g_kh[(nb + 2 * jj + 1) * HD + t] = __float2half(hi);
        unpack2(av[jj], lo, hi);
        g_vth[t * N_NODES + (nb + 2 * jj)]     = __float2half(lo);
        g_vth[t * N_NODES + (nb + 2 * jj + 1)] = __float2half(hi);
    }
}

// ---------------------------------------------------------------------------
// Kernel 2: f16 tensor-core flash attention (m16n8k16, fp32 accumulate).
// Block = 64 queries x 1 head, 4 warps; warp owns 16 query rows.
//  - h2exp2 on packed score pairs: output IS the PV A-fragment (k-pair layout
//    2tid,2tid+1 == C-layout columns) — zero shuffles/packs.
//  - Row sums via a 3rd MMA with B=ones (fp32-exact, no LDS, no reduction).
//  - Ks stride 24 halves (12 words), Vt_s stride 136 halves (68 words):
//    all B-fragment LDS patterns hit 32 distinct banks (g*12+tid, g*4+tid).
// ---------------------------------------------------------------------------
__global__ void attn_kernel() {
    const int h = blockIdx.y;
    const int qbase = blockIdx.x * 64;
    const int t = threadIdx.x;          // 0..127
    const int w = t >> 5;
    const int lane = t & 31;
    const int g = lane >> 2;            // 0..7
    const int tid = lane & 3;           // 0..3

    __shared__ __align__(16) uint32_t Ksw[128 * 12];  // K tile: [key][24 halves]
    __shared__ __align__(16) uint32_t Vsw[16 * 68];   // Vt tile: [d][136 halves]

    // Q A-fragment: direct packed loads (pre-scaled f16 pairs)
    uint32_t qa[4];
    {
        const __half* Q0 = g_qh + (qbase + w * 16 + g) * HD + h * D;
        const __half* Q1 = Q0 + 8 * HD;
        qa[0] = *(const uint32_t*)(Q0 + 2 * tid);
        qa[1] = *(const uint32_t*)(Q1 + 2 * tid);
        qa[2] = *(const uint32_t*)(Q0 + 2 * tid + 8);
        qa[3] = *(const uint32_t*)(Q1 + 2 * tid + 8);
    }

    float o0[4] = {0.f, 0.f, 0.f, 0.f};    // O d-cols 0..7  (rows g, g+8)
    float o1[4] = {0.f, 0.f, 0.f, 0.f};    // O d-cols 8..15
    float lacc[4] = {0.f, 0.f, 0.f, 0.f};  // row sums via ones-MMA
    const uint32_t ONES = 0x3C003C00u;     // f16x2 {1,1}

    const int vrow = t & 15;               // Vt row this thread loads
    const int vchunk = t >> 4;              // 0..7, 16 keys each

    for (int kt = 0; kt < N_NODES; kt += 128) {
        __syncthreads();
        {
            // K: thread t loads key kt+t (16 halves = 32B)
            const uint4* kp = (const uint4*)(g_kh + (kt + t) * HD + h * D);
            uint4* kd = (uint4*)(Ksw + t * 12);
            kd[0] = kp[0];
            kd[1] = kp[1];
            // Vt: thread t loads row vrow, keys [kt+16*vchunk, +16)
            const uint4* vp = (const uint4*)(g_vth + (h * D + vrow) * N_NODES + kt + vchunk * 16);
            uint4* vd = (uint4*)(Vsw + vrow * 68 + vchunk * 8);
            vd[0] = vp[0];
            vd[1] = vp[1];
        }
        __syncthreads();

#pragma unroll
        for (int u = 0; u < 8; u++) {       // 16 keys per iteration
            float scA[4] = {0.f, 0.f, 0.f, 0.f};
            float scB[4] = {0.f, 0.f, 0.f, 0.f};
            const int kA = (16 * u + g) * 12;
            const int kB = (16 * u + 8 + g) * 12;
            mma_f16(scA, qa, Ksw[kA + tid], Ksw[kA + 4 + tid]);
            mma_f16(scB, qa, Ksw[kB + tid], Ksw[kB + 4 + tid]);
            // p = 2^S' ; packed pairs are the PV A-fragment directly
            uint32_t pa[4];
            pa[0] = h2bits(h2exp2(__floats2half2_rn(scA[0], scA[1])));  // row g,   k 2tid,2tid+1
            pa[1] = h2bits(h2exp2(__floats2half2_rn(scA[2], scA[3])));  // row g+8, k 2tid,2tid+1
            pa[2] = h2bits(h2exp2(__floats2half2_rn(scB[0], scB[1])));  // row g,   k 2tid+8
            pa[3] = h2bits(h2exp2(__floats2half2_rn(scB[2], scB[3])));  // row g+8, k 2tid+8
            const int vb = 8 * u + tid;
            mma_f16(o0, pa, Vsw[g * 68 + vb],       Vsw[g * 68 + 4 + vb]);
            mma_f16(o1, pa, Vsw[(g + 8) * 68 + vb], Vsw[(g + 8) * 68 + 4 + vb]);
            mma_f16(lacc, pa, ONES, ONES);
        }
    }

    const float i0 = 1.f / lacc[0];   // row g full sum
    const float i1 = 1.f / lacc[2];   // row g+8 full sum

    float* O0 = &g_attn[(qbase + w * 16 + g) * HD + h * D];
    float* O1 = O0 + 8 * HD;
    *(float2*)&O0[2 * tid]     = make_float2(o0[0] * i0, o0[1] * i0);
    *(float2*)&O1[2 * tid]     = make_float2(o0[2] * i1, o0[3] * i1);
    *(float2*)&O0[2 * tid + 8] = make_float2(o1[0] * i0, o1[1] * i0);
    *(float2*)&O1[2 * tid + 8] = make_float2(o1[2] * i1, o1[3] * i1);
}

// ---------------------------------------------------------------------------
// Kernel 3: out proj + residual + LayerNorm. 8 nodes/block, Wo smem-tiled,
// LN via per-warp shuffle reductions (warp w owns nodes 2w, 2w+1).
// ---------------------------------------------------------------------------
#define ONODES 8
__global__ void out_kernel(const float* __restrict__ s,
                           const float* __restrict__ Wo, const float* __restrict__ bo,
                           const float* __restrict__ gamma, const float* __restrict__ beta,
                           float* __restrict__ out) {
    const int nb = blockIdx.x * ONODES;
    const int t = threadIdx.x;
    const int w = t >> 5;
    const int lane = t & 31;
    __shared__ __align__(16) float a_t[HD][ONODES];
    __shared__ __align__(16) float wsm[16 * 128];
    __shared__ float vals[ONODES][128];
    __shared__ float mus[ONODES], ivs[ONODES];

    for (int idx = t; idx < HD * ONODES; idx += 128) {
        const int j = idx & 7;
        const int i = idx >> 3;
        a_t[i][j] = g_attn[(nb + j) * HD + i];
    }

    const float bov = bo[t];
    u64 acc[4];
#pragma unroll
    for (int jj = 0; jj < 4; jj++) acc[jj] = pack2(bov, bov);

    for (int kt = 0; kt < 8; kt++) {
        __syncthreads();
        {
            const float4* so4 = (const float4*)(Wo + kt * 16 * 128);
            float4* dw = (float4*)wsm;
#pragma unroll
            for (int p = 0; p < 4; p++) dw[t + p * 128] = so4[t + p * 128];
        }
        __syncthreads();
#pragma unroll
        for (int ii = 0; ii < 16; ii++) {
            const int i = kt * 16 + ii;
            const float wv = wsm[ii * 128 + t];
            const u64 w2 = pack2(wv, wv);
            const ulonglong2* cr = (const ulonglong2*)a_t[i];
            const ulonglong2 ca = cr[0], cb = cr[1];
            acc[0] = fma2(w2, ca.x, acc[0]); acc[1] = fma2(w2, ca.y, acc[1]);
            acc[2] = fma2(w2, cb.x, acc[2]); acc[3] = fma2(w2, cb.y, acc[3]);
        }
    }

    float val[8];
#pragma unroll
    for (int jj = 0; jj < 4; jj++) unpack2(acc[jj], val[2 * jj], val[2 * jj + 1]);
#pragma unroll
    for (int j = 0; j < 8; j++) {
        val[j] += s[(nb + j) * NS + t];
        vals[j][t] = val[j];
    }
    __syncthreads();

    // warp w reduces nodes 2w, 2w+1 (sum + sumsq over 128 channels)
#pragma unroll
    for (int jj = 0; jj < 2; jj++) {
        const int j = w * 2 + jj;
        float sv = 0.f, sq = 0.f;
#pragma unroll
        for (int c = 0; c < 4; c++) {
            const float x = vals[j][lane + 32 * c];
            sv += x;
            sq = fmaf(x, x, sq);
        }
#pragma unroll
        for (int off = 16; off > 0; off >>= 1) {
            sv += __shfl_xor_sync(0xffffffffu, sv, off);
            sq += __shfl_xor_sync(0xffffffffu, sq, off);
        }
        if (lane == 0) {
            const float mu = sv * (1.f / 128.f);
            mus[j] = mu;
            ivs[j] = rsqrtf(sq * (1.f / 128.f) - mu * mu + 1e-5f);
        }
    }
    __syncthreads();

    const float gm = gamma[t], bt = beta[t];
#pragma unroll
    for (int j = 0; j < 8; j++) {
        out[(nb + j) * NS + t] = (val[j] - mus[j]) * ivs[j] * gm + bt;
    }
}

// ---------------------------------------------------------------------------
extern "C" void kernel_launch(void* const* d_in, const int* in_sizes, int n_in,
                              void* d_out, int out_size) {
    const float* s     = (const float*)d_in[0];
    const float* v     = (const float*)d_in[1];
    const float* Wq    = (const float*)d_in[2];
    const float* bq    = (const float*)d_in[3];
    const float* Wk    = (const float*)d_in[4];
    const float* bk    = (const float*)d_in[5];
    const float* Wv    = (const float*)d_in[6];
    const float* bv    = (const float*)d_in[7];
    const float* Wo    = (const float*)d_in[8];
    const float* bo    = (const float*)d_in[9];
    const float* gamma = (const float*)d_in[10];
    const float* beta  = (const float*)d_in[11];
    float* out = (float*)d_out;

    proj_kernel<<<N_NODES / PNODES, 128>>>(s, v, Wq, bq, Wk, bk, Wv, bv);
    attn_kernel<<<dim3(N_NODES / 64, H), 128>>>();
    out_kernel<<<N_NODES / ONODES, 128>>>(s, Wo, bo, gamma, beta, out);

    // v passes through unchanged: second element of the output tuple
    cudaMemcpyAsync(out + N_NODES * NS, v, N_NODES * NV * 3 * sizeof(float),
                    cudaMemcpyDeviceToDevice, 0);
}

// round 6
// speedup vs baseline: 4.1570x; 1.1271x over previous
#include <cuda_runtime.h>
#include <cuda_fp16.h>
#include <cstdint>

#define N_NODES 4096
#define NS 128
#define NV 16
#define H 8
#define D 16
#define COMB 144
#define HD 128   // H*D

typedef unsigned long long u64;

// ---- packed f32x2 helpers (proj/out GEMVs) ----
__device__ __forceinline__ u64 pack2(float lo, float hi) {
    u64 d; asm("mov.b64 %0, {%1, %2};" : "=l"(d) : "f"(lo), "f"(hi)); return d;
}
__device__ __forceinline__ void unpack2(u64 x, float& lo, float& hi) {
    asm("mov.b64 {%0, %1}, %2;" : "=f"(lo), "=f"(hi) : "l"(x));
}
__device__ __forceinline__ u64 fma2(u64 a, u64 b, u64 c) {
    u64 d; asm("fma.rn.f32x2 %0, %1, %2, %3;" : "=l"(d) : "l"(a), "l"(b), "l"(c)); return d;
}
// ---- f16 mma (m16n8k16, fp32 accumulate) ----
__device__ __forceinline__ void mma_f16(float* d, const uint32_t* a, uint32_t b0, uint32_t b1) {
    asm("mma.sync.aligned.m16n8k16.row.col.f32.f16.f16.f32 "
        "{%0,%1,%2,%3},{%4,%5,%6,%7},{%8,%9},{%0,%1,%2,%3};"
        : "+f"(d[0]), "+f"(d[1]), "+f"(d[2]), "+f"(d[3])
        : "r"(a[0]), "r"(a[1]), "r"(a[2]), "r"(a[3]), "r"(b0), "r"(b1));
}
__device__ __forceinline__ uint32_t h2bits(__half2 h) {
    return *reinterpret_cast<uint32_t*>(&h);
}
// ---- cp.async helpers ----
__device__ __forceinline__ void cp16(void* smem_dst, const void* gsrc) {
    uint32_t d = (uint32_t)__cvta_generic_to_shared(smem_dst);
    asm volatile("cp.async.cg.shared.global [%0], [%1], 16;" :: "r"(d), "l"(gsrc));
}
__device__ __forceinline__ void cp_commit() {
    asm volatile("cp.async.commit_group;");
}
template <int N>
__device__ __forceinline__ void cp_wait() {
    asm volatile("cp.async.wait_group %0;" :: "n"(N) : "memory");
}
__device__ __forceinline__ void barx(int id) {   // 128-thread named barrier
    asm volatile("bar.sync %0, 128;" :: "r"(id) : "memory");
}

// Scratch (static device globals — no allocation allowed)
__device__ __half g_qh[N_NODES * HD];   // q * (D^-0.5 * log2e), f16, [node][ch]
__device__ __half g_kh[N_NODES * HD];   // k, f16, [node][ch]
__device__ __half g_vth[HD * N_NODES];  // v, f16, TRANSPOSED [ch][node]
__device__ float  g_attn[N_NODES * HD];

// ---------------------------------------------------------------------------
// Kernel 1: projections, 8 nodes/block. Weight tiles double-buffered via
// cp.async so L2 latency never sits on the critical path.
// ---------------------------------------------------------------------------
#define PNODES 8
__global__ void proj_kernel(const float* __restrict__ s, const float* __restrict__ v,
                            const float* __restrict__ Wq, const float* __restrict__ bq,
                            const float* __restrict__ Wk, const float* __restrict__ bk,
                            const float* __restrict__ Wv, const float* __restrict__ bv) {
    const int nb = blockIdx.x * PNODES;
    const int t = threadIdx.x;
    __shared__ __align__(16) float comb_t[COMB][PNODES];
    __shared__ __align__(16) float wsm[2][2][16 * 128];   // [buf][array][tile]

    for (int idx = t; idx < COMB * PNODES; idx += 128) {
        const int j = idx & 7;
        const int i = idx >> 3;
        float val;
        if (i < NS) {
            val = s[(nb + j) * NS + i];
        } else {
            const int vi = i - NS;
            const float* vp = &v[(nb + j) * NV * 3 + vi * 3];
            float x = vp[0], y = vp[1], z = vp[2];
            val = sqrtf(fmaxf(x * x + y * y + z * z, 1e-8f));
        }
        comb_t[i][j] = val;
    }

    const float bqv = bq[t], bkv = bk[t], bvv = bv[t];
    u64 aq[4], ak[4], av[4];
#pragma unroll
    for (int jj = 0; jj < 4; jj++) {
        aq[jj] = pack2(bqv, bqv);
        ak[jj] = pack2(bkv, bkv);
        av[jj] = pack2(bvv, bvv);
    }

    // ---- Phase A: Wq+Wk over COMB=144 (9 tiles), cp.async double buffer ----
    {
        // issue tile 0 -> buf 0
#pragma unroll
        for (int p = 0; p < 4; p++) {
            cp16(&((float4*)wsm[0][0])[t + p * 128], (const float4*)Wq + t + p * 128);
            cp16(&((float4*)wsm[0][1])[t + p * 128], (const float4*)Wk + t + p * 128);
        }
        cp_commit();
        for (int kt = 0; kt < 9; kt++) {
            if (kt < 8) {
                const int nb_ = (kt + 1) & 1;
                const float4* sq4 = (const float4*)(Wq + (kt + 1) * 2048);
                const float4* sk4 = (const float4*)(Wk + (kt + 1) * 2048);
#pragma unroll
                for (int p = 0; p < 4; p++) {
                    cp16(&((float4*)wsm[nb_][0])[t + p * 128], sq4 + t + p * 128);
                    cp16(&((float4*)wsm[nb_][1])[t + p * 128], sk4 + t + p * 128);
                }
                cp_commit();
                cp_wait<1>();
            } else {
                cp_wait<0>();
            }
            __syncthreads();
            const int b = kt & 1;
#pragma unroll
            for (int ii = 0; ii < 16; ii++) {
                const int i = kt * 16 + ii;
                const float wq = wsm[b][0][ii * 128 + t];
                const float wk = wsm[b][1][ii * 128 + t];
                const u64 wq2 = pack2(wq, wq);
                const u64 wk2 = pack2(wk, wk);
                const ulonglong2* cr = (const ulonglong2*)comb_t[i];
                const ulonglong2 ca = cr[0], cb = cr[1];
                aq[0] = fma2(wq2, ca.x, aq[0]); aq[1] = fma2(wq2, ca.y, aq[1]);
                aq[2] = fma2(wq2, cb.x, aq[2]); aq[3] = fma2(wq2, cb.y, aq[3]);
                ak[0] = fma2(wk2, ca.x, ak[0]); ak[1] = fma2(wk2, ca.y, ak[1]);
                ak[2] = fma2(wk2, cb.x, ak[2]); ak[3] = fma2(wk2, cb.y, ak[3]);
            }
            __syncthreads();   // protect buf reuse by next issue
        }
    }
    // ---- Phase B: Wv over NS=128 (8 tiles), cp.async double buffer ----
    {
#pragma unroll
        for (int p = 0; p < 4; p++)
            cp16(&((float4*)wsm[0][0])[t + p * 128], (const float4*)Wv + t + p * 128);
        cp_commit();
        for (int kt = 0; kt < 8; kt++) {
            if (kt < 7) {
                const int nb_ = (kt + 1) & 1;
                const float4* sv4 = (const float4*)(Wv + (kt + 1) * 2048);
#pragma unroll
                for (int p = 0; p < 4; p++)
                    cp16(&((float4*)wsm[nb_][0])[t + p * 128], sv4 + t + p * 128);
                cp_commit();
                cp_wait<1>();
            } else {
                cp_wait<0>();
            }
            __syncthreads();
            const int b = kt & 1;
#pragma unroll
            for (int ii = 0; ii < 16; ii++) {
                const int i = kt * 16 + ii;
                const float wv = wsm[b][0][ii * 128 + t];
                const u64 wv2 = pack2(wv, wv);
                const ulonglong2* cr = (const ulonglong2*)comb_t[i];
                const ulonglong2 ca = cr[0], cb = cr[1];
                av[0] = fma2(wv2, ca.x, av[0]); av[1] = fma2(wv2, ca.y, av[1]);
                av[2] = fma2(wv2, cb.x, av[2]); av[3] = fma2(wv2, cb.y, av[3]);
            }
            __syncthreads();
        }
    }

    const float CS = 0.25f * 1.4426950408889634f;  // D^-0.5 * log2(e), folded into q
#pragma unroll
    for (int jj = 0; jj < 4; jj++) {
        float lo, hi;
        unpack2(aq[jj], lo, hi);
        g_qh[(nb + 2 * jj) * HD + t]     = __float2half(lo * CS);
        g_qh[(nb + 2 * jj + 1) * HD + t] = __float2half(hi * CS);
        unpack2(ak[jj], lo, hi);
        g_kh[(nb + 2 * jj) * HD + t]     = __float2half(lo);
        g_kh[(nb + 2 * jj + 1) * HD + t] = __float2half(hi);
        unpack2(av[jj], lo, hi);
        g_vth[t * N_NODES + (nb + 2 * jj)]     = __float2half(lo);
        g_vth[t * N_NODES + (nb + 2 * jj + 1)] = __float2half(hi);
    }
}

// ---------------------------------------------------------------------------
// Kernel 2: f16 tensor-core flash attention, 8 warps/block with in-block
// split-K: warp-group 0 handles even 128-key tiles, group 1 odd tiles, for
// the SAME 64 queries. Groups use private smem tiles + private named
// barriers (never couple), then fp32 partials (o, l) merge once via smem.
//  - h2exp2 packed output IS the PV A-fragment (no shuffles/packs).
//  - Row sums via ones-MMA (fp32-exact).
// ---------------------------------------------------------------------------
__global__ void attn_kernel() {
    const int h = blockIdx.y;
    const int qbase = blockIdx.x * 64;
    const int gid = threadIdx.x >> 7;   // key-split group 0/1
    const int tl = threadIdx.x & 127;
    const int w = tl >> 5;
    const int lane = tl & 31;
    const int g = lane >> 2;
    const int tid = lane & 3;

    __shared__ __align__(16) uint32_t Ksw[2][128 * 12];
    __shared__ __align__(16) uint32_t Vsw[2][16 * 68];
    __shared__ float mrg[128][10];

    uint32_t qa[4];
    {
        const __half* Q0 = g_qh + (qbase + w * 16 + g) * HD + h * D;
        const __half* Q1 = Q0 + 8 * HD;
        qa[0] = *(const uint32_t*)(Q0 + 2 * tid);
        qa[1] = *(const uint32_t*)(Q1 + 2 * tid);
        qa[2] = *(const uint32_t*)(Q0 + 2 * tid + 8);
        qa[3] = *(const uint32_t*)(Q1 + 2 * tid + 8);
    }

    float o0[4] = {0.f, 0.f, 0.f, 0.f};
    float o1[4] = {0.f, 0.f, 0.f, 0.f};
    float lacc[4] = {0.f, 0.f, 0.f, 0.f};
    const uint32_t ONES = 0x3C003C00u;

    const int vrow = tl & 15;
    const int vchunk = tl >> 4;
    uint32_t* Kg = Ksw[gid];
    uint32_t* Vg = Vsw[gid];

    for (int i = 0; i < 16; i++) {
        const int kt = (2 * i + gid) * 128;
        barx(1 + gid);
        {
            const uint4* kp = (const uint4*)(g_kh + (kt + tl) * HD + h * D);
            uint4* kd = (uint4*)(Kg + tl * 12);
            kd[0] = kp[0];
            kd[1] = kp[1];
            const uint4* vp = (const uint4*)(g_vth + (h * D + vrow) * N_NODES + kt + vchunk * 16);
            uint4* vd = (uint4*)(Vg + vrow * 68 + vchunk * 8);
            vd[0] = vp[0];
            vd[1] = vp[1];
        }
        barx(1 + gid);

#pragma unroll
        for (int u = 0; u < 8; u++) {       // 16 keys
            float scA[4] = {0.f, 0.f, 0.f, 0.f};
            float scB[4] = {0.f, 0.f, 0.f, 0.f};
            const int kA = (16 * u + g) * 12;
            const int kB = (16 * u + 8 + g) * 12;
            mma_f16(scA, qa, Kg[kA + tid], Kg[kA + 4 + tid]);
            mma_f16(scB, qa, Kg[kB + tid], Kg[kB + 4 + tid]);
            uint32_t pa[4];
            pa[0] = h2bits(h2exp2(__floats2half2_rn(scA[0], scA[1])));
            pa[1] = h2bits(h2exp2(__floats2half2_rn(scA[2], scA[3])));
            pa[2] = h2bits(h2exp2(__floats2half2_rn(scB[0], scB[1])));
            pa[3] = h2bits(h2exp2(__floats2half2_rn(scB[2], scB[3])));
            const int vb = 8 * u + tid;
            mma_f16(o0, pa, Vg[g * 68 + vb],       Vg[g * 68 + 4 + vb]);
            mma_f16(o1, pa, Vg[(g + 8) * 68 + vb], Vg[(g + 8) * 68 + 4 + vb]);
            mma_f16(lacc, pa, ONES, ONES);
        }
    }

    // merge split-K partials (fp32) through smem
    if (gid == 1) {
        float* m = mrg[tl];
        m[0] = o0[0]; m[1] = o0[1]; m[2] = o0[2]; m[3] = o0[3];
        m[4] = o1[0]; m[5] = o1[1]; m[6] = o1[2]; m[7] = o1[3];
        m[8] = lacc[0]; m[9] = lacc[2];
    }
    __syncthreads();
    if (gid == 0) {
        const float* m = mrg[tl];
        const float i0 = 1.f / (lacc[0] + m[8]);
        const float i1 = 1.f / (lacc[2] + m[9]);
        float* O0 = &g_attn[(qbase + w * 16 + g) * HD + h * D];
        float* O1 = O0 + 8 * HD;
        *(float2*)&O0[2 * tid]     = make_float2((o0[0] + m[0]) * i0, (o0[1] + m[1]) * i0);
        *(float2*)&O1[2 * tid]     = make_float2((o0[2] + m[2]) * i1, (o0[3] + m[3]) * i1);
        *(float2*)&O0[2 * tid + 8] = make_float2((o1[0] + m[4]) * i0, (o1[1] + m[5]) * i0);
        *(float2*)&O1[2 * tid + 8] = make_float2((o1[2] + m[6]) * i1, (o1[3] + m[7]) * i1);
    }
}

// ---------------------------------------------------------------------------
// Kernel 3: out proj + residual + LayerNorm. 8 nodes/block, Wo smem-tiled,
// LN via per-warp shuffle reductions (warp w owns nodes 2w, 2w+1).
// ---------------------------------------------------------------------------
#define ONODES 8
__global__ void out_kernel(const float* __restrict__ s,
                           const float* __restrict__ Wo, const float* __restrict__ bo,
                           const float* __restrict__ gamma, const float* __restrict__ beta,
                           float* __restrict__ out) {
    const int nb = blockIdx.x * ONODES;
    const int t = threadIdx.x;
    const int w = t >> 5;
    const int lane = t & 31;
    __shared__ __align__(16) float a_t[HD][ONODES];
    __shared__ __align__(16) float wsm[2][16 * 128];
    __shared__ float vals[ONODES][128];
    __shared__ float mus[ONODES], ivs[ONODES];

    for (int idx = t; idx < HD * ONODES; idx += 128) {
        const int j = idx & 7;
        const int i = idx >> 3;
        a_t[i][j] = g_attn[(nb + j) * HD + i];
    }

    const float bov = bo[t];
    u64 acc[4];
#pragma unroll
    for (int jj = 0; jj < 4; jj++) acc[jj] = pack2(bov, bov);

    // cp.async double-buffered Wo tiles
#pragma unroll
    for (int p = 0; p < 4; p++)
        cp16(&((float4*)wsm[0])[t + p * 128], (const float4*)Wo + t + p * 128);
    cp_commit();
    for (int kt = 0; kt < 8; kt++) {
        if (kt < 7) {
            const int nb_ = (kt + 1) & 1;
            const float4* so4 = (const float4*)(Wo + (kt + 1) * 2048);
#pragma unroll
            for (int p = 0; p < 4; p++)
                cp16(&((float4*)wsm[nb_])[t + p * 128], so4 + t + p * 128);
            cp_commit();
            cp_wait<1>();
        } else {
            cp_wait<0>();
        }
        __syncthreads();
        const int b = kt & 1;
#pragma unroll
        for (int ii = 0; ii < 16; ii++) {
            const int i = kt * 16 + ii;
            const float wv = wsm[b][ii * 128 + t];
            const u64 w2 = pack2(wv, wv);
            const ulonglong2* cr = (const ulonglong2*)a_t[i];
            const ulonglong2 ca = cr[0], cb = cr[1];
            acc[0] = fma2(w2, ca.x, acc[0]); acc[1] = fma2(w2, ca.y, acc[1]);
            acc[2] = fma2(w2, cb.x, acc[2]); acc[3] = fma2(w2, cb.y, acc[3]);
        }
        __syncthreads();
    }

    float val[8];
#pragma unroll
    for (int jj = 0; jj < 4; jj++) unpack2(acc[jj], val[2 * jj], val[2 * jj + 1]);
#pragma unroll
    for (int j = 0; j < 8; j++) {
        val[j] += s[(nb + j) * NS + t];
        vals[j][t] = val[j];
    }
    __syncthreads();

#pragma unroll
    for (int jj = 0; jj < 2; jj++) {
        const int j = w * 2 + jj;
        float sv = 0.f, sq = 0.f;
#pragma unroll
        for (int c = 0; c < 4; c++) {
            const float x = vals[j][lane + 32 * c];
            sv += x;
            sq = fmaf(x, x, sq);
        }
#pragma unroll
        for (int off = 16; off > 0; off >>= 1) {
            sv += __shfl_xor_sync(0xffffffffu, sv, off);
            sq += __shfl_xor_sync(0xffffffffu, sq, off);
        }
        if (lane == 0) {
            const float mu = sv * (1.f / 128.f);
            mus[j] = mu;
            ivs[j] = rsqrtf(sq * (1.f / 128.f) - mu * mu + 1e-5f);
        }
    }
    __syncthreads();

    const float gm = gamma[t], bt = beta[t];
#pragma unroll
    for (int j = 0; j < 8; j++) {
        out[(nb + j) * NS + t] = (val[j] - mus[j]) * ivs[j] * gm + bt;
    }
}

// ---------------------------------------------------------------------------
extern "C" void kernel_launch(void* const* d_in, const int* in_sizes, int n_in,
                              void* d_out, int out_size) {
    const float* s     = (const float*)d_in[0];
    const float* v     = (const float*)d_in[1];
    const float* Wq    = (const float*)d_in[2];
    const float* bq    = (const float*)d_in[3];
    const float* Wk    = (const float*)d_in[4];
    const float* bk    = (const float*)d_in[5];
    const float* Wv    = (const float*)d_in[6];
    const float* bv    = (const float*)d_in[7];
    const float* Wo    = (const float*)d_in[8];
    const float* bo    = (const float*)d_in[9];
    const float* gamma = (const float*)d_in[10];
    const float* beta  = (const float*)d_in[11];
    float* out = (float*)d_out;

    proj_kernel<<<N_NODES / PNODES, 128>>>(s, v, Wq, bq, Wk, bk, Wv, bv);
    attn_kernel<<<dim3(N_NODES / 64, H), 256>>>();
    out_kernel<<<N_NODES / ONODES, 128>>>(s, Wo, bo, gamma, beta, out);

    // v passes through unchanged: second element of the output tuple
    cudaMemcpyAsync(out + N_NODES * NS, v, N_NODES * NV * 3 * sizeof(float),
                    cudaMemcpyDeviceToDevice, 0);
}